// round 2
// baseline (speedup 1.0000x reference)
#include <cuda_runtime.h>
#include <math.h>

#define BB 32
#define NN 1024
#define DD 64
#define HALF (BB*NN*DD)

// ---------------- scratch (device globals; no allocation allowed) ----------
static __device__ float g_sigF[(size_t)BB*NN*NN];   // 128 MB
static __device__ float g_sigG[(size_t)BB*NN*NN];   // 128 MB
static __device__ float g_EF  [(size_t)BB*NN*NN];   // E_pre -> (softmax(E) - I + Amix)
static __device__ float g_NG  [(size_t)BB*NN*NN];   // N_pre -> N_hat
static __device__ float g_e1f[BB*NN], g_e2f[BB*NN], g_e1g[BB*NN], g_e2g[BB*NN];
static __device__ float g_Amix[NN*NN];
static __device__ float g_What[DD*DD];
static __device__ float g_salpha[NN];

__device__ __forceinline__ float sigm(float v) { return 1.0f / (1.0f + __expf(-v)); }

// ---------------- kernel 1a: e1/e2 row dots (4 weight vectors at once) -----
__global__ void k_evec(const float* __restrict__ x,
                       const float* __restrict__ fw1, const float* __restrict__ fw2,
                       const float* __restrict__ gw1, const float* __restrict__ gw2) {
    int gwarp = (blockIdx.x * blockDim.x + threadIdx.x) >> 5;  // 0..B*N-1
    int lane  = threadIdx.x & 31;
    const float* xp = x + (size_t)gwarp * DD;
    float v0 = xp[lane], v1 = xp[lane + 32];
    float s0 = v0 * fw1[lane] + v1 * fw1[lane + 32];
    float s1 = v0 * fw2[lane] + v1 * fw2[lane + 32];
    float s2 = v0 * gw1[lane] + v1 * gw1[lane + 32];
    float s3 = v0 * gw2[lane] + v1 * gw2[lane + 32];
    #pragma unroll
    for (int o = 16; o > 0; o >>= 1) {
        s0 += __shfl_xor_sync(0xffffffffu, s0, o);
        s1 += __shfl_xor_sync(0xffffffffu, s1, o);
        s2 += __shfl_xor_sync(0xffffffffu, s2, o);
        s3 += __shfl_xor_sync(0xffffffffu, s3, o);
    }
    if (lane == 0) {
        g_e1f[gwarp] = s0; g_e2f[gwarp] = s1;
        g_e1g[gwarp] = s2; g_e2g[gwarp] = s3;
    }
}

// ---------------- kernel 1b: A_mix = cw0*adj0 + cw1*adj1 - (cw0+cw1)*I -----
__global__ void k_amix(const float* __restrict__ adj, const float* __restrict__ convw) {
    int t = blockIdx.x * blockDim.x + threadIdx.x;   // 0..N*N/4-1
    int base = t * 4;
    int i = base >> 10;
    int j = base & (NN - 1);
    float c0 = convw[0], c1 = convw[1];
    float dsub = c0 + c1;
    float4 a0 = *(const float4*)(adj + base);
    float4 a1 = *(const float4*)(adj + (size_t)NN * NN + base);
    float4 r;
    r.x = c0 * a0.x + c1 * a1.x - ((i == j + 0) ? dsub : 0.0f);
    r.y = c0 * a0.y + c1 * a1.y - ((i == j + 1) ? dsub : 0.0f);
    r.z = c0 * a0.z + c1 * a1.z - ((i == j + 2) ? dsub : 0.0f);
    r.w = c0 * a0.w + c1 * a1.w - ((i == j + 3) ? dsub : 0.0f);
    *(float4*)(g_Amix + base) = r;
}

// ---------------- kernel 1c: W_hat = (w*clip(d)) @ w.T - I -----------------
__global__ void k_what(const float* __restrict__ w, const float* __restrict__ d) {
    int t = blockIdx.x * blockDim.x + threadIdx.x;   // 0..4095
    int i = t >> 6, j = t & 63;
    float s = 0.0f;
    #pragma unroll 8
    for (int k = 0; k < DD; k++) {
        float dc = fminf(fmaxf(d[k], 0.0f), 1.0f);
        s += w[i * DD + k] * dc * w[j * DD + k];
    }
    g_What[t] = s - ((i == j) ? 1.0f : 0.0f);
}

// ---------------- kernel 1d: sigmoid(alpha) --------------------------------
__global__ void k_salpha(const float* __restrict__ alpha) {
    int t = blockIdx.x * blockDim.x + threadIdx.x;
    if (t < NN) g_salpha[t] = sigm(alpha[t]);
}

// ---------------- kernel 2: sig[b,j,k] = sigmoid(e1[b,j]*e2[b,k]+bs[j,k]) --
__global__ void k_sig(const float* __restrict__ fbs, const float* __restrict__ gbs) {
    int j = blockIdx.x, b = blockIdx.y, which = blockIdx.z;
    int k = threadIdx.x * 4;
    const float* e1 = which ? g_e1g : g_e1f;
    const float* e2 = which ? g_e2g : g_e2f;
    const float* bs = which ? gbs : fbs;
    float* outp = (which ? g_sigG : g_sigF) + ((size_t)b * NN + j) * NN + k;
    float  a   = e1[b * NN + j];
    float4 e2v = *(const float4*)(e2 + b * NN + k);
    float4 bv  = *(const float4*)(bs + (size_t)j * NN + k);
    float4 r;
    r.x = sigm(a * e2v.x + bv.x);
    r.y = sigm(a * e2v.y + bv.y);
    r.z = sigm(a * e2v.z + bv.z);
    r.w = sigm(a * e2v.w + bv.w);
    *(float4*)outp = r;
}

// ---------------- kernel 3: batched SGEMM  C[b] = vs @ sig[b] --------------
// 128x128 tile, K-chunk 8, double-buffered smem, 8x8 per thread.
__global__ void __launch_bounds__(256) k_gemm(const float* __restrict__ vsF,
                                              const float* __restrict__ vsG) {
    int z = blockIdx.z;
    int b = z & (BB - 1);
    int which = z >> 5;
    const float* __restrict__ A  = which ? vsG : vsF;
    const float* __restrict__ Bm = (which ? g_sigG : g_sigF) + (size_t)b * NN * NN;
    float* __restrict__ C        = (which ? g_NG  : g_EF  ) + (size_t)b * NN * NN;
    int i0 = blockIdx.y * 128, j0 = blockIdx.x * 128;

    __shared__ float As[2][8][128];
    __shared__ float Bs[2][8][128];

    int tid = threadIdx.x;
    int ar = tid >> 1, ak = (tid & 1) * 4;
    int br = tid >> 5, bc = (tid & 31) * 4;
    int r0 = (tid >> 4) * 8, c0 = (tid & 15) * 8;

    float acc[8][8];
    #pragma unroll
    for (int r = 0; r < 8; r++)
        #pragma unroll
        for (int c = 0; c < 8; c++) acc[r][c] = 0.0f;

    // preload tile 0
    {
        float4 a4 = *(const float4*)(A  + (size_t)(i0 + ar) * NN + ak);
        float4 b4 = *(const float4*)(Bm + (size_t)br * NN + j0 + bc);
        As[0][ak + 0][ar] = a4.x; As[0][ak + 1][ar] = a4.y;
        As[0][ak + 2][ar] = a4.z; As[0][ak + 3][ar] = a4.w;
        *(float4*)&Bs[0][br][bc] = b4;
    }
    __syncthreads();

    for (int kt = 0; kt < 128; ++kt) {
        int cur = kt & 1;
        float4 a4n, b4n;
        if (kt < 127) {
            int k0 = (kt + 1) * 8;
            a4n = *(const float4*)(A  + (size_t)(i0 + ar) * NN + k0 + ak);
            b4n = *(const float4*)(Bm + (size_t)(k0 + br) * NN + j0 + bc);
        }
        #pragma unroll
        for (int kk = 0; kk < 8; kk++) {
            float a[8], bb[8];
            *(float4*)&a[0]  = *(float4*)&As[cur][kk][r0];
            *(float4*)&a[4]  = *(float4*)&As[cur][kk][r0 + 4];
            *(float4*)&bb[0] = *(float4*)&Bs[cur][kk][c0];
            *(float4*)&bb[4] = *(float4*)&Bs[cur][kk][c0 + 4];
            #pragma unroll
            for (int r = 0; r < 8; r++)
                #pragma unroll
                for (int c = 0; c < 8; c++)
                    acc[r][c] += a[r] * bb[c];
        }
        if (kt < 127) {
            int nxt = cur ^ 1;
            As[nxt][ak + 0][ar] = a4n.x; As[nxt][ak + 1][ar] = a4n.y;
            As[nxt][ak + 2][ar] = a4n.z; As[nxt][ak + 3][ar] = a4n.w;
            *(float4*)&Bs[nxt][br][bc] = b4n;
            __syncthreads();
        }
    }

    #pragma unroll
    for (int r = 0; r < 8; r++) {
        float* cp = C + (size_t)(i0 + r0 + r) * NN + j0 + c0;
        *(float4*)cp       = make_float4(acc[r][0], acc[r][1], acc[r][2], acc[r][3]);
        *(float4*)(cp + 4) = make_float4(acc[r][4], acc[r][5], acc[r][6], acc[r][7]);
    }
}

// ---------------- kernel 4: row softmax of E_pre/N_pre; fuse N_hat + Emod --
__global__ void k_soft() {
    int i = blockIdx.x, b = blockIdx.y;
    size_t ro = ((size_t)b * NN + i) * NN;
    int c = threadIdx.x * 4;
    int wid = threadIdx.x >> 5, lane = threadIdx.x & 31;
    __shared__ float sE[8], sN[8];

    float4 ev = *(float4*)(g_EF + ro + c);
    float4 nv = *(float4*)(g_NG + ro + c);

    float mE = fmaxf(fmaxf(ev.x, ev.y), fmaxf(ev.z, ev.w));
    float mN = fmaxf(fmaxf(nv.x, nv.y), fmaxf(nv.z, nv.w));
    #pragma unroll
    for (int o = 16; o > 0; o >>= 1) {
        mE = fmaxf(mE, __shfl_xor_sync(0xffffffffu, mE, o));
        mN = fmaxf(mN, __shfl_xor_sync(0xffffffffu, mN, o));
    }
    if (lane == 0) { sE[wid] = mE; sN[wid] = mN; }
    __syncthreads();
    mE = sE[0]; mN = sN[0];
    #pragma unroll
    for (int wv = 1; wv < 8; wv++) { mE = fmaxf(mE, sE[wv]); mN = fmaxf(mN, sN[wv]); }
    __syncthreads();

    float4 eE, eN;
    eE.x = __expf(ev.x - mE); eE.y = __expf(ev.y - mE);
    eE.z = __expf(ev.z - mE); eE.w = __expf(ev.w - mE);
    eN.x = __expf(nv.x - mN); eN.y = __expf(nv.y - mN);
    eN.z = __expf(nv.z - mN); eN.w = __expf(nv.w - mN);
    float sumE = eE.x + eE.y + eE.z + eE.w;
    float sumN = eN.x + eN.y + eN.z + eN.w;
    #pragma unroll
    for (int o = 16; o > 0; o >>= 1) {
        sumE += __shfl_xor_sync(0xffffffffu, sumE, o);
        sumN += __shfl_xor_sync(0xffffffffu, sumN, o);
    }
    if (lane == 0) { sE[wid] = sumE; sN[wid] = sumN; }
    __syncthreads();
    sumE = 0.0f; sumN = 0.0f;
    #pragma unroll
    for (int wv = 0; wv < 8; wv++) { sumE += sE[wv]; sumN += sN[wv]; }

    float invE = __fdividef(1.0f, sumE);
    float invN = __fdividef(1.0f, sumN);

    float4 se;
    se.x = eE.x * invE; se.y = eE.y * invE; se.z = eE.z * invE; se.w = eE.w * invE;
    float4 nh;
    nh.x = __fdividef(eN.x * invN, se.x + 1e-5f);
    nh.y = __fdividef(eN.y * invN, se.y + 1e-5f);
    nh.z = __fdividef(eN.z * invN, se.z + 1e-5f);
    nh.w = __fdividef(eN.w * invN, se.w + 1e-5f);

    float4 am = *(float4*)(g_Amix + (size_t)i * NN + c);
    float4 em;
    em.x = se.x + am.x - ((c + 0 == i) ? 1.0f : 0.0f);
    em.y = se.y + am.y - ((c + 1 == i) ? 1.0f : 0.0f);
    em.z = se.z + am.z - ((c + 2 == i) ? 1.0f : 0.0f);
    em.w = se.w + am.w - ((c + 3 == i) ? 1.0f : 0.0f);

    *(float4*)(g_EF + ro + c) = em;
    *(float4*)(g_NG + ro + c) = nh;
}

// ---------------- kernel 5: f = tanh(Emod@xr + xw + x0*sa + cb); g = tanh(Nhat@xr)
// 64 rows x 64 cols per block; coefficient tiles padded (stride 65) in smem.
#define K5_SMEM_FLOATS (64*65 + 64*65 + 64*64)
__global__ void __launch_bounds__(256) k_final(const float* __restrict__ x,
                                               const float* __restrict__ x0,
                                               const float* __restrict__ convb,
                                               float* __restrict__ out) {
    extern __shared__ float sm[];
    float* Es = sm;                 // 64*65
    float* Ns = sm + 64 * 65;       // 64*65
    float* xs = sm + 2 * 64 * 65;   // 64*64 (16B-aligned offset)

    int b = blockIdx.y, i0 = blockIdx.x * 64;
    int tid = threadIdx.x;
    int il = tid >> 2, cg = tid & 3, c0 = cg * 16;
    const float* xr = x    + (size_t)b * NN * DD;
    const float* Em = g_EF + (size_t)b * NN * NN;
    const float* Nh = g_NG + (size_t)b * NN * NN;

    float af[16], ag[16];
    #pragma unroll
    for (int q = 0; q < 16; q++) { af[q] = 0.0f; ag[q] = 0.0f; }

    for (int jc = 0; jc < 16; jc++) {
        #pragma unroll
        for (int q = 0; q < 4; q++) {
            int lin = tid + q * 256;
            int row = lin >> 4, cc = (lin & 15) * 4;
            float4 ev = *(const float4*)(Em + (size_t)(i0 + row) * NN + jc * 64 + cc);
            Es[row * 65 + cc + 0] = ev.x; Es[row * 65 + cc + 1] = ev.y;
            Es[row * 65 + cc + 2] = ev.z; Es[row * 65 + cc + 3] = ev.w;
            float4 nv = *(const float4*)(Nh + (size_t)(i0 + row) * NN + jc * 64 + cc);
            Ns[row * 65 + cc + 0] = nv.x; Ns[row * 65 + cc + 1] = nv.y;
            Ns[row * 65 + cc + 2] = nv.z; Ns[row * 65 + cc + 3] = nv.w;
            *(float4*)&xs[row * 64 + cc] =
                *(const float4*)(xr + (size_t)(jc * 64 + row) * DD + cc);
        }
        __syncthreads();
        #pragma unroll 8
        for (int j = 0; j < 64; j++) {
            float cf  = Es[il * 65 + j];
            float cgv = Ns[il * 65 + j];
            #pragma unroll
            for (int q = 0; q < 4; q++) {
                float4 xv = *(float4*)&xs[j * 64 + c0 + q * 4];
                af[q * 4 + 0] += cf * xv.x;  af[q * 4 + 1] += cf * xv.y;
                af[q * 4 + 2] += cf * xv.z;  af[q * 4 + 3] += cf * xv.w;
                ag[q * 4 + 0] += cgv * xv.x; ag[q * 4 + 1] += cgv * xv.y;
                ag[q * 4 + 2] += cgv * xv.z; ag[q * 4 + 3] += cgv * xv.w;
            }
        }
        __syncthreads();
    }

    // epilogue: xw = xr_i @ W_hat  (W_hat -> xs (stride 64), Xi -> Es (stride 65))
    #pragma unroll
    for (int q = 0; q < 4; q++) {
        int lin = tid + q * 256;
        int row = lin >> 4, cc = (lin & 15) * 4;
        *(float4*)&xs[row * 64 + cc] = *(const float4*)(g_What + row * DD + cc);
        float4 xiv = *(const float4*)(xr + (size_t)(i0 + row) * DD + cc);
        Es[row * 65 + cc + 0] = xiv.x; Es[row * 65 + cc + 1] = xiv.y;
        Es[row * 65 + cc + 2] = xiv.z; Es[row * 65 + cc + 3] = xiv.w;
    }
    __syncthreads();
    #pragma unroll 8
    for (int k = 0; k < DD; k++) {
        float xik = Es[il * 65 + k];
        #pragma unroll
        for (int q = 0; q < 4; q++) {
            float4 wv = *(float4*)&xs[k * 64 + c0 + q * 4];
            af[q * 4 + 0] += xik * wv.x; af[q * 4 + 1] += xik * wv.y;
            af[q * 4 + 2] += xik * wv.z; af[q * 4 + 3] += xik * wv.w;
        }
    }

    float cb = convb[0];
    float sa = g_salpha[i0 + il];
    size_t obase = ((size_t)b * NN + i0 + il) * DD + c0;
    #pragma unroll
    for (int q = 0; q < 4; q++) {
        float4 x0v = *(const float4*)(x0 + obase + q * 4);
        float4 fo, go;
        fo.x = tanhf(af[q * 4 + 0] + cb + x0v.x * sa);
        fo.y = tanhf(af[q * 4 + 1] + cb + x0v.y * sa);
        fo.z = tanhf(af[q * 4 + 2] + cb + x0v.z * sa);
        fo.w = tanhf(af[q * 4 + 3] + cb + x0v.w * sa);
        go.x = tanhf(ag[q * 4 + 0]);
        go.y = tanhf(ag[q * 4 + 1]);
        go.z = tanhf(ag[q * 4 + 2]);
        go.w = tanhf(ag[q * 4 + 3]);
        *(float4*)(out + obase + q * 4)        = fo;
        *(float4*)(out + HALF + obase + q * 4) = go;
    }
}

// ---------------- launch ----------------------------------------------------
extern "C" void kernel_launch(void* const* d_in, const int* in_sizes, int n_in,
                              void* d_out, int out_size) {
    const float* x     = (const float*)d_in[0];
    const float* x0    = (const float*)d_in[1];
    const float* w     = (const float*)d_in[2];
    const float* d     = (const float*)d_in[3];
    const float* alpha = (const float*)d_in[4];
    const float* fw1   = (const float*)d_in[5];
    const float* fw2   = (const float*)d_in[6];
    const float* fvs   = (const float*)d_in[7];
    const float* fbs   = (const float*)d_in[8];
    const float* gw1   = (const float*)d_in[9];
    const float* gw2   = (const float*)d_in[10];
    const float* gvs   = (const float*)d_in[11];
    const float* gbs   = (const float*)d_in[12];
    const float* convw = (const float*)d_in[13];
    const float* convb = (const float*)d_in[14];
    const float* adj   = (const float*)d_in[15];
    float* out = (float*)d_out;

    cudaFuncSetAttribute(k_final, cudaFuncAttributeMaxDynamicSharedMemorySize,
                         K5_SMEM_FLOATS * (int)sizeof(float));

    k_evec  <<<(BB * NN) / 8, 256>>>(x, fw1, fw2, gw1, gw2);
    k_amix  <<<(NN * NN / 4) / 256, 256>>>(adj, convw);
    k_what  <<<(DD * DD) / 256, 256>>>(w, d);
    k_salpha<<<NN / 256, 256>>>(alpha);
    k_sig   <<<dim3(NN, BB, 2), 256>>>(fbs, gbs);
    k_gemm  <<<dim3(8, 8, 2 * BB), 256>>>(fvs, gvs);
    k_soft  <<<dim3(NN, BB), 256>>>();
    k_final <<<dim3(NN / 64, BB), 256, K5_SMEM_FLOATS * (int)sizeof(float)>>>(x, x0, convb, out);
}

// round 5
// speedup vs baseline: 1.6115x; 1.6115x over previous
#include <cuda_runtime.h>
#include <cuda_bf16.h>
#include <math.h>
#include <stdint.h>

#define BB 32
#define NN 1024
#define DD 64
#define HALF (BB*NN*DD)

// ---------------- scratch (device globals; no allocation allowed) ----------
static __device__ __nv_bfloat16 g_sHi[(size_t)2*BB*NN*NN];  // sigmoid hi [which][b][n][j]
static __device__ __nv_bfloat16 g_sLo[(size_t)2*BB*NN*NN];  // sigmoid lo
static __device__ __nv_bfloat16 g_vHi[(size_t)2*NN*NN];     // vs hi [which][i][j]
static __device__ __nv_bfloat16 g_vLo[(size_t)2*NN*NN];     // vs lo
static __device__ float g_EF  [(size_t)BB*NN*NN];   // E_pre -> (softmax(E) - I + Amix)
static __device__ float g_NG  [(size_t)BB*NN*NN];   // N_pre -> N_hat
static __device__ float g_bsTf[(size_t)NN*NN];
static __device__ float g_bsTg[(size_t)NN*NN];
static __device__ float g_e1f[BB*NN], g_e2f[BB*NN], g_e1g[BB*NN], g_e2g[BB*NN];
static __device__ float g_Amix[NN*NN];
static __device__ float g_What[DD*DD];
static __device__ float g_salpha[NN];

__device__ __forceinline__ float sigm(float v) { return 1.0f / (1.0f + __expf(-v)); }
__device__ __forceinline__ uint32_t smem_u32(const void* p) {
    uint32_t a;
    asm("{ .reg .u64 t; cvta.to.shared.u64 t, %1; cvt.u32.u64 %0, t; }" : "=r"(a) : "l"(p));
    return a;
}
// split x = hi + lo (bf16 each)
__device__ __forceinline__ void bf16_split(float x, __nv_bfloat16& hi, __nv_bfloat16& lo) {
    hi = __float2bfloat16(x);
    lo = __float2bfloat16(x - __bfloat162float(hi));
}
__device__ __forceinline__ void mma16(float* c, const uint32_t* a, const uint32_t* b) {
    asm volatile("mma.sync.aligned.m16n8k16.row.col.f32.bf16.bf16.f32 "
                 "{%0,%1,%2,%3}, {%4,%5,%6,%7}, {%8,%9}, {%0,%1,%2,%3};"
                 : "+f"(c[0]), "+f"(c[1]), "+f"(c[2]), "+f"(c[3])
                 : "r"(a[0]), "r"(a[1]), "r"(a[2]), "r"(a[3]),
                   "r"(b[0]), "r"(b[1]));
}

// ---------------- kernel 1a: e1/e2 row dots --------------------------------
__global__ void k_evec(const float* __restrict__ x,
                       const float* __restrict__ fw1, const float* __restrict__ fw2,
                       const float* __restrict__ gw1, const float* __restrict__ gw2) {
    int gwarp = (blockIdx.x * blockDim.x + threadIdx.x) >> 5;
    int lane  = threadIdx.x & 31;
    const float* xp = x + (size_t)gwarp * DD;
    float v0 = xp[lane], v1 = xp[lane + 32];
    float s0 = v0 * fw1[lane] + v1 * fw1[lane + 32];
    float s1 = v0 * fw2[lane] + v1 * fw2[lane + 32];
    float s2 = v0 * gw1[lane] + v1 * gw1[lane + 32];
    float s3 = v0 * gw2[lane] + v1 * gw2[lane + 32];
    #pragma unroll
    for (int o = 16; o > 0; o >>= 1) {
        s0 += __shfl_xor_sync(0xffffffffu, s0, o);
        s1 += __shfl_xor_sync(0xffffffffu, s1, o);
        s2 += __shfl_xor_sync(0xffffffffu, s2, o);
        s3 += __shfl_xor_sync(0xffffffffu, s3, o);
    }
    if (lane == 0) {
        g_e1f[gwarp] = s0; g_e2f[gwarp] = s1;
        g_e1g[gwarp] = s2; g_e2g[gwarp] = s3;
    }
}

// ---------------- kernel 1b: A_mix -----------------------------------------
__global__ void k_amix(const float* __restrict__ adj, const float* __restrict__ convw) {
    int t = blockIdx.x * blockDim.x + threadIdx.x;
    int base = t * 4;
    int i = base >> 10;
    int j = base & (NN - 1);
    float c0 = convw[0], c1 = convw[1];
    float dsub = c0 + c1;
    float4 a0 = *(const float4*)(adj + base);
    float4 a1 = *(const float4*)(adj + (size_t)NN * NN + base);
    float4 r;
    r.x = c0 * a0.x + c1 * a1.x - ((i == j + 0) ? dsub : 0.0f);
    r.y = c0 * a0.y + c1 * a1.y - ((i == j + 1) ? dsub : 0.0f);
    r.z = c0 * a0.z + c1 * a1.z - ((i == j + 2) ? dsub : 0.0f);
    r.w = c0 * a0.w + c1 * a1.w - ((i == j + 3) ? dsub : 0.0f);
    *(float4*)(g_Amix + base) = r;
}

// ---------------- kernel 1c: W_hat -----------------------------------------
__global__ void k_what(const float* __restrict__ w, const float* __restrict__ d) {
    int t = blockIdx.x * blockDim.x + threadIdx.x;
    int i = t >> 6, j = t & 63;
    float s = 0.0f;
    #pragma unroll 8
    for (int k = 0; k < DD; k++) {
        float dc = fminf(fmaxf(d[k], 0.0f), 1.0f);
        s += w[i * DD + k] * dc * w[j * DD + k];
    }
    g_What[t] = s - ((i == j) ? 1.0f : 0.0f);
}

// ---------------- kernel 1d: sigmoid(alpha) --------------------------------
__global__ void k_salpha(const float* __restrict__ alpha) {
    int t = blockIdx.x * blockDim.x + threadIdx.x;
    if (t < NN) g_salpha[t] = sigm(alpha[t]);
}

// ---------------- kernel 1e: transpose fbs/gbs -----------------------------
__global__ void k_transp(const float* __restrict__ fbs, const float* __restrict__ gbs) {
    __shared__ float t[32][33];
    const float* src = blockIdx.z ? gbs : fbs;
    float* dst = blockIdx.z ? g_bsTg : g_bsTf;
    int x0 = blockIdx.x * 32, y0 = blockIdx.y * 32;
    #pragma unroll
    for (int r = threadIdx.y; r < 32; r += 8)
        t[r][threadIdx.x] = src[(size_t)(y0 + r) * NN + x0 + threadIdx.x];
    __syncthreads();
    #pragma unroll
    for (int r = threadIdx.y; r < 32; r += 8)
        dst[(size_t)(x0 + r) * NN + y0 + threadIdx.x] = t[threadIdx.x][r];
}

// ---------------- kernel 1f: bf16-split vs ---------------------------------
__global__ void k_split(const float* __restrict__ fvs, const float* __restrict__ gvs) {
    int t = blockIdx.x * blockDim.x + threadIdx.x;   // over 2*N*N/4
    int which = t >= (NN * NN / 4);
    int e = which ? t - NN * NN / 4 : t;
    const float4* src = (const float4*)(which ? gvs : fvs);
    float4 a = src[e];
    __nv_bfloat16 h0, l0, h1, l1, h2, l2, h3, l3;
    bf16_split(a.x, h0, l0); bf16_split(a.y, h1, l1);
    bf16_split(a.z, h2, l2); bf16_split(a.w, h3, l3);
    size_t off = (size_t)which * NN * NN + (size_t)e * 4;
    __nv_bfloat162* ph = (__nv_bfloat162*)(g_vHi + off);
    __nv_bfloat162* pl = (__nv_bfloat162*)(g_vLo + off);
    ph[0] = __nv_bfloat162{h0, h1}; ph[1] = __nv_bfloat162{h2, h3};
    pl[0] = __nv_bfloat162{l0, l1}; pl[1] = __nv_bfloat162{l2, l3};
}

// -------- kernel 2: S[b,n,j] = sigmoid(e2[b,n]*e1[b,j] + bsT[n,j]), hi/lo --
__global__ void k_sig(void) {
    int n = blockIdx.x, b = blockIdx.y, which = blockIdx.z;
    int j = threadIdx.x * 4;
    const float* e1 = which ? g_e1g : g_e1f;
    const float* e2 = which ? g_e2g : g_e2f;
    const float* bsT = (which ? g_bsTg : g_bsTf) + (size_t)n * NN + j;
    size_t off = (((size_t)which * BB + b) * NN + n) * NN + j;
    float  a   = e2[b * NN + n];
    float4 e1v = *(const float4*)(e1 + b * NN + j);
    float4 bv  = *(const float4*)bsT;
    float sx = sigm(a * e1v.x + bv.x);
    float sy = sigm(a * e1v.y + bv.y);
    float sz = sigm(a * e1v.z + bv.z);
    float sw = sigm(a * e1v.w + bv.w);
    __nv_bfloat16 h0, l0, h1, l1, h2, l2, h3, l3;
    bf16_split(sx, h0, l0); bf16_split(sy, h1, l1);
    bf16_split(sz, h2, l2); bf16_split(sw, h3, l3);
    __nv_bfloat162* ph = (__nv_bfloat162*)(g_sHi + off);
    __nv_bfloat162* pl = (__nv_bfloat162*)(g_sLo + off);
    ph[0] = __nv_bfloat162{h0, h1}; ph[1] = __nv_bfloat162{h2, h3};
    pl[0] = __nv_bfloat162{l0, l1}; pl[1] = __nv_bfloat162{l2, l3};
}

// ---------------- kernel 3: bf16x3 mma.sync batched GEMM -------------------
// C[b][i][n] = sum_j vs[i][j] * S[b][n][j]
// Split: C = Ahi*Bhi + Ahi*Blo + Alo*Bhi  (all bf16, fp32 accum)
// CTA 128x128, 8 warps (2x4), warp tile 64x32, K-tile 16, cp.async double buf.
#define KT     16
#define STRW   12                 // smem row stride in 32-bit words (24 bf16)
#define TILE_W (128*STRW)         // 1536 words = 6KB per tile
#define GEMM_SMEM (2*4*TILE_W*4)  // 49152 bytes

__global__ void __launch_bounds__(256) k_gemm() {
    extern __shared__ uint32_t smw[];
    int tid = threadIdx.x;
    int z = blockIdx.z;
    int b = z & (BB - 1);
    int which = z >> 5;
    const __nv_bfloat16* __restrict__ Ahi = g_vHi + (size_t)which * NN * NN;
    const __nv_bfloat16* __restrict__ Alo = g_vLo + (size_t)which * NN * NN;
    const __nv_bfloat16* __restrict__ Bhi = g_sHi + ((size_t)which * BB + b) * NN * NN;
    const __nv_bfloat16* __restrict__ Blo = g_sLo + ((size_t)which * BB + b) * NN * NN;
    float* __restrict__ C = (which ? g_NG : g_EF) + (size_t)b * NN * NN;
    int i0 = blockIdx.y * 128, n0 = blockIdx.x * 128;

    int wid = tid >> 5, lane = tid & 31;
    int gid = lane >> 2, tg = lane & 3;
    int wm = (wid & 1) * 64, wn = (wid >> 1) * 32;

    float acc[4][4][4];
    #pragma unroll
    for (int mf = 0; mf < 4; mf++)
        #pragma unroll
        for (int nf = 0; nf < 4; nf++)
            #pragma unroll
            for (int q = 0; q < 4; q++) acc[mf][nf][q] = 0.0f;

    // one stage = 4 tiles (Ahi,Alo,Bhi,Blo) x 128 rows x 16 bf16 (2x16B chunks)
    #define ISSUE_STAGE(S) do {                                                  \
        uint32_t sb_ = smem_u32(smw + ((S) & 1) * 4 * TILE_W);                   \
        int kc_ = (S) * KT;                                                      \
        _Pragma("unroll")                                                        \
        for (int it = 0; it < 4; it++) {                                         \
            int slot = tid + it * 256;                                           \
            int tile = slot >> 8;                                                \
            int r2 = slot & 255;                                                 \
            int row = r2 >> 1, c = r2 & 1;                                       \
            const __nv_bfloat16* src =                                           \
                (tile == 0) ? Ahi + (size_t)(i0 + row) * NN :                    \
                (tile == 1) ? Alo + (size_t)(i0 + row) * NN :                    \
                (tile == 2) ? Bhi + (size_t)(n0 + row) * NN :                    \
                              Blo + (size_t)(n0 + row) * NN;                     \
            const char* gp = (const char*)(src + kc_) + c * 16;                  \
            uint32_t sp = sb_ + (uint32_t)(tile * TILE_W + row * STRW + c * 4) * 4u; \
            asm volatile("cp.async.ca.shared.global [%0], [%1], 16;"             \
                         :: "r"(sp), "l"(gp));                                   \
        }                                                                        \
        asm volatile("cp.async.commit_group;");                                  \
    } while (0)

    ISSUE_STAGE(0);
    for (int s = 0; s < NN / KT; s++) {
        if (s < NN / KT - 1) {
            ISSUE_STAGE(s + 1);
            asm volatile("cp.async.wait_group 1;");
        } else {
            asm volatile("cp.async.wait_group 0;");
        }
        __syncthreads();
        const uint32_t* base = smw + (s & 1) * 4 * TILE_W;
        const uint32_t* wAh = base;
        const uint32_t* wAl = base + TILE_W;
        const uint32_t* wBh = base + 2 * TILE_W;
        const uint32_t* wBl = base + 3 * TILE_W;

        uint32_t ah[4][4], al[4][4], bh[4][2], bl[4][2];
        #pragma unroll
        for (int mf = 0; mf < 4; mf++) {
            int m = wm + mf * 16;
            int r0w = (m + gid) * STRW, r1w = (m + gid + 8) * STRW;
            ah[mf][0] = wAh[r0w + tg];     ah[mf][1] = wAh[r1w + tg];
            ah[mf][2] = wAh[r0w + 4 + tg]; ah[mf][3] = wAh[r1w + 4 + tg];
            al[mf][0] = wAl[r0w + tg];     al[mf][1] = wAl[r1w + tg];
            al[mf][2] = wAl[r0w + 4 + tg]; al[mf][3] = wAl[r1w + 4 + tg];
        }
        #pragma unroll
        for (int nf = 0; nf < 4; nf++) {
            int n = wn + nf * 8;
            int rw = (n + gid) * STRW;
            bh[nf][0] = wBh[rw + tg]; bh[nf][1] = wBh[rw + 4 + tg];
            bl[nf][0] = wBl[rw + tg]; bl[nf][1] = wBl[rw + 4 + tg];
        }
        #pragma unroll
        for (int mf = 0; mf < 4; mf++)
            #pragma unroll
            for (int nf = 0; nf < 4; nf++) {
                mma16(acc[mf][nf], ah[mf], bh[nf]);
                mma16(acc[mf][nf], ah[mf], bl[nf]);
                mma16(acc[mf][nf], al[mf], bh[nf]);
            }
        __syncthreads();
    }

    // epilogue: direct float2 stores
    #pragma unroll
    for (int mf = 0; mf < 4; mf++) {
        #pragma unroll
        for (int nf = 0; nf < 4; nf++) {
            int row = i0 + wm + mf * 16 + gid;
            int col = n0 + wn + nf * 8 + tg * 2;
            float2 v0 = make_float2(acc[mf][nf][0], acc[mf][nf][1]);
            float2 v1 = make_float2(acc[mf][nf][2], acc[mf][nf][3]);
            *(float2*)(C + (size_t)row * NN + col)       = v0;
            *(float2*)(C + (size_t)(row + 8) * NN + col) = v1;
        }
    }
}

// ---------------- kernel 4: row softmax; fuse N_hat + Emod -----------------
__global__ void k_soft() {
    int i = blockIdx.x, b = blockIdx.y;
    size_t ro = ((size_t)b * NN + i) * NN;
    int c = threadIdx.x * 4;
    int wid = threadIdx.x >> 5, lane = threadIdx.x & 31;
    __shared__ float sE[8], sN[8];

    float4 ev = *(float4*)(g_EF + ro + c);
    float4 nv = *(float4*)(g_NG + ro + c);

    float mE = fmaxf(fmaxf(ev.x, ev.y), fmaxf(ev.z, ev.w));
    float mN = fmaxf(fmaxf(nv.x, nv.y), fmaxf(nv.z, nv.w));
    #pragma unroll
    for (int o = 16; o > 0; o >>= 1) {
        mE = fmaxf(mE, __shfl_xor_sync(0xffffffffu, mE, o));
        mN = fmaxf(mN, __shfl_xor_sync(0xffffffffu, mN, o));
    }
    if (lane == 0) { sE[wid] = mE; sN[wid] = mN; }
    __syncthreads();
    mE = sE[0]; mN = sN[0];
    #pragma unroll
    for (int wv = 1; wv < 8; wv++) { mE = fmaxf(mE, sE[wv]); mN = fmaxf(mN, sN[wv]); }
    __syncthreads();

    float4 eE, eN;
    eE.x = __expf(ev.x - mE); eE.y = __expf(ev.y - mE);
    eE.z = __expf(ev.z - mE); eE.w = __expf(ev.w - mE);
    eN.x = __expf(nv.x - mN); eN.y = __expf(nv.y - mN);
    eN.z = __expf(nv.z - mN); eN.w = __expf(nv.w - mN);
    float sumE = eE.x + eE.y + eE.z + eE.w;
    float sumN = eN.x + eN.y + eN.z + eN.w;
    #pragma unroll
    for (int o = 16; o > 0; o >>= 1) {
        sumE += __shfl_xor_sync(0xffffffffu, sumE, o);
        sumN += __shfl_xor_sync(0xffffffffu, sumN, o);
    }
    if (lane == 0) { sE[wid] = sumE; sN[wid] = sumN; }
    __syncthreads();
    sumE = 0.0f; sumN = 0.0f;
    #pragma unroll
    for (int wv = 0; wv < 8; wv++) { sumE += sE[wv]; sumN += sN[wv]; }

    float invE = __fdividef(1.0f, sumE);
    float invN = __fdividef(1.0f, sumN);

    float4 se;
    se.x = eE.x * invE; se.y = eE.y * invE; se.z = eE.z * invE; se.w = eE.w * invE;
    float4 nh;
    nh.x = __fdividef(eN.x * invN, se.x + 1e-5f);
    nh.y = __fdividef(eN.y * invN, se.y + 1e-5f);
    nh.z = __fdividef(eN.z * invN, se.z + 1e-5f);
    nh.w = __fdividef(eN.w * invN, se.w + 1e-5f);

    float4 am = *(float4*)(g_Amix + (size_t)i * NN + c);
    float4 em;
    em.x = se.x + am.x - ((c + 0 == i) ? 1.0f : 0.0f);
    em.y = se.y + am.y - ((c + 1 == i) ? 1.0f : 0.0f);
    em.z = se.z + am.z - ((c + 2 == i) ? 1.0f : 0.0f);
    em.w = se.w + am.w - ((c + 3 == i) ? 1.0f : 0.0f);

    *(float4*)(g_EF + ro + c) = em;
    *(float4*)(g_NG + ro + c) = nh;
}

// ---------------- kernel 5: fused finals -----------------------------------
#define K5_SMEM_FLOATS (64*65 + 64*65 + 64*64)
__global__ void __launch_bounds__(256) k_final(const float* __restrict__ x,
                                               const float* __restrict__ x0,
                                               const float* __restrict__ convb,
                                               float* __restrict__ out) {
    extern __shared__ float smf[];
    float* Es = smf;
    float* Ns = smf + 64 * 65;
    float* xs = smf + 2 * 64 * 65;

    int b = blockIdx.y, i0 = blockIdx.x * 64;
    int tid = threadIdx.x;
    int il = tid >> 2, cg = tid & 3, c0 = cg * 16;
    const float* xr = x    + (size_t)b * NN * DD;
    const float* Em = g_EF + (size_t)b * NN * NN;
    const float* Nh = g_NG + (size_t)b * NN * NN;

    float af[16], ag[16];
    #pragma unroll
    for (int q = 0; q < 16; q++) { af[q] = 0.0f; ag[q] = 0.0f; }

    for (int jc = 0; jc < 16; jc++) {
        #pragma unroll
        for (int q = 0; q < 4; q++) {
            int lin = tid + q * 256;
            int row = lin >> 4, cc = (lin & 15) * 4;
            float4 ev = *(const float4*)(Em + (size_t)(i0 + row) * NN + jc * 64 + cc);
            Es[row * 65 + cc + 0] = ev.x; Es[row * 65 + cc + 1] = ev.y;
            Es[row * 65 + cc + 2] = ev.z; Es[row * 65 + cc + 3] = ev.w;
            float4 nv = *(const float4*)(Nh + (size_t)(i0 + row) * NN + jc * 64 + cc);
            Ns[row * 65 + cc + 0] = nv.x; Ns[row * 65 + cc + 1] = nv.y;
            Ns[row * 65 + cc + 2] = nv.z; Ns[row * 65 + cc + 3] = nv.w;
            *(float4*)&xs[row * 64 + cc] =
                *(const float4*)(xr + (size_t)(jc * 64 + row) * DD + cc);
        }
        __syncthreads();
        #pragma unroll 8
        for (int j = 0; j < 64; j++) {
            float cf  = Es[il * 65 + j];
            float cgv = Ns[il * 65 + j];
            #pragma unroll
            for (int q = 0; q < 4; q++) {
                float4 xv = *(float4*)&xs[j * 64 + c0 + q * 4];
                af[q * 4 + 0] += cf * xv.x;  af[q * 4 + 1] += cf * xv.y;
                af[q * 4 + 2] += cf * xv.z;  af[q * 4 + 3] += cf * xv.w;
                ag[q * 4 + 0] += cgv * xv.x; ag[q * 4 + 1] += cgv * xv.y;
                ag[q * 4 + 2] += cgv * xv.z; ag[q * 4 + 3] += cgv * xv.w;
            }
        }
        __syncthreads();
    }

    #pragma unroll
    for (int q = 0; q < 4; q++) {
        int lin = tid + q * 256;
        int row = lin >> 4, cc = (lin & 15) * 4;
        *(float4*)&xs[row * 64 + cc] = *(const float4*)(g_What + row * DD + cc);
        float4 xiv = *(const float4*)(xr + (size_t)(i0 + row) * DD + cc);
        Es[row * 65 + cc + 0] = xiv.x; Es[row * 65 + cc + 1] = xiv.y;
        Es[row * 65 + cc + 2] = xiv.z; Es[row * 65 + cc + 3] = xiv.w;
    }
    __syncthreads();
    #pragma unroll 8
    for (int k = 0; k < DD; k++) {
        float xik = Es[il * 65 + k];
        #pragma unroll
        for (int q = 0; q < 4; q++) {
            float4 wv = *(float4*)&xs[k * 64 + c0 + q * 4];
            af[q * 4 + 0] += xik * wv.x; af[q * 4 + 1] += xik * wv.y;
            af[q * 4 + 2] += xik * wv.z; af[q * 4 + 3] += xik * wv.w;
        }
    }

    float cb = convb[0];
    float sa = g_salpha[i0 + il];
    size_t obase = ((size_t)b * NN + i0 + il) * DD + c0;
    #pragma unroll
    for (int q = 0; q < 4; q++) {
        float4 x0v = *(const float4*)(x0 + obase + q * 4);
        float4 fo, go;
        fo.x = tanhf(af[q * 4 + 0] + cb + x0v.x * sa);
        fo.y = tanhf(af[q * 4 + 1] + cb + x0v.y * sa);
        fo.z = tanhf(af[q * 4 + 2] + cb + x0v.z * sa);
        fo.w = tanhf(af[q * 4 + 3] + cb + x0v.w * sa);
        go.x = tanhf(ag[q * 4 + 0]);
        go.y = tanhf(ag[q * 4 + 1]);
        go.z = tanhf(ag[q * 4 + 2]);
        go.w = tanhf(ag[q * 4 + 3]);
        *(float4*)(out + obase + q * 4)        = fo;
        *(float4*)(out + HALF + obase + q * 4) = go;
    }
}

// ---------------- launch ----------------------------------------------------
extern "C" void kernel_launch(void* const* d_in, const int* in_sizes, int n_in,
                              void* d_out, int out_size) {
    const float* x     = (const float*)d_in[0];
    const float* x0    = (const float*)d_in[1];
    const float* w     = (const float*)d_in[2];
    const float* d     = (const float*)d_in[3];
    const float* alpha = (const float*)d_in[4];
    const float* fw1   = (const float*)d_in[5];
    const float* fw2   = (const float*)d_in[6];
    const float* fvs   = (const float*)d_in[7];
    const float* fbs   = (const float*)d_in[8];
    const float* gw1   = (const float*)d_in[9];
    const float* gw2   = (const float*)d_in[10];
    const float* gvs   = (const float*)d_in[11];
    const float* gbs   = (const float*)d_in[12];
    const float* convw = (const float*)d_in[13];
    const float* convb = (const float*)d_in[14];
    const float* adj   = (const float*)d_in[15];
    float* out = (float*)d_out;

    cudaFuncSetAttribute(k_final, cudaFuncAttributeMaxDynamicSharedMemorySize,
                         K5_SMEM_FLOATS * (int)sizeof(float));
    cudaFuncSetAttribute(k_gemm, cudaFuncAttributeMaxDynamicSharedMemorySize, GEMM_SMEM);

    k_evec  <<<(BB * NN) / 8, 256>>>(x, fw1, fw2, gw1, gw2);
    k_amix  <<<(NN * NN / 4) / 256, 256>>>(adj, convw);
    k_what  <<<(DD * DD) / 256, 256>>>(w, d);
    k_salpha<<<NN / 256, 256>>>(alpha);
    k_transp<<<dim3(32, 32, 2), dim3(32, 8)>>>(fbs, gbs);
    k_split <<<(2 * NN * NN / 4) / 256, 256>>>(fvs, gvs);
    k_sig   <<<dim3(NN, BB, 2), 256>>>();
    k_gemm  <<<dim3(NN / 128, NN / 128, 2 * BB), 256, GEMM_SMEM>>>();
    k_soft  <<<dim3(NN, BB), 256>>>();
    k_final <<<dim3(NN / 64, BB), 256, K5_SMEM_FLOATS * (int)sizeof(float)>>>(x, x0, convb, out);
}

// round 6
// speedup vs baseline: 1.7942x; 1.1134x over previous
#include <cuda_runtime.h>
#include <cuda_bf16.h>
#include <math.h>
#include <stdint.h>

#define BB 32
#define NN 1024
#define DD 64
#define HALF (BB*NN*DD)

// ---------------- scratch (device globals; no allocation allowed) ----------
static __device__ __nv_bfloat16 g_sHi[(size_t)2*BB*NN*NN];  // sigmoid hi [which][b][n][j]
static __device__ __nv_bfloat16 g_sLo[(size_t)2*BB*NN*NN];  // sigmoid lo
static __device__ __nv_bfloat16 g_vHi[(size_t)2*NN*NN];     // vs hi [which][i][j]
static __device__ __nv_bfloat16 g_vLo[(size_t)2*NN*NN];     // vs lo
static __device__ float g_EF  [(size_t)BB*NN*NN];   // E_pre -> (softmax(E) - I + Amix)
static __device__ float g_NG  [(size_t)BB*NN*NN];   // N_pre -> N_hat
static __device__ float g_bsTf[(size_t)NN*NN];
static __device__ float g_bsTg[(size_t)NN*NN];
static __device__ float g_e1f[BB*NN], g_e2f[BB*NN], g_e1g[BB*NN], g_e2g[BB*NN];
static __device__ float g_Amix[NN*NN];
static __device__ float g_What[DD*DD];
static __device__ float g_salpha[NN];

__device__ __forceinline__ float sigm(float v) { return 1.0f / (1.0f + __expf(-v)); }
__device__ __forceinline__ uint32_t smem_u32(const void* p) {
    uint32_t a;
    asm("{ .reg .u64 t; cvta.to.shared.u64 t, %1; cvt.u32.u64 %0, t; }" : "=r"(a) : "l"(p));
    return a;
}
__device__ __forceinline__ void bf16_split(float x, __nv_bfloat16& hi, __nv_bfloat16& lo) {
    hi = __float2bfloat16(x);
    lo = __float2bfloat16(x - __bfloat162float(hi));
}
__device__ __forceinline__ void mma16(float* c, const uint32_t* a, const uint32_t* b) {
    asm volatile("mma.sync.aligned.m16n8k16.row.col.f32.bf16.bf16.f32 "
                 "{%0,%1,%2,%3}, {%4,%5,%6,%7}, {%8,%9}, {%0,%1,%2,%3};"
                 : "+f"(c[0]), "+f"(c[1]), "+f"(c[2]), "+f"(c[3])
                 : "r"(a[0]), "r"(a[1]), "r"(a[2]), "r"(a[3]),
                   "r"(b[0]), "r"(b[1]));
}
__device__ __forceinline__ void ldm_x4(uint32_t* r, uint32_t addr) {
    asm volatile("ldmatrix.sync.aligned.m8n8.x4.shared.b16 {%0,%1,%2,%3}, [%4];"
                 : "=r"(r[0]), "=r"(r[1]), "=r"(r[2]), "=r"(r[3]) : "r"(addr));
}

// ---------------- kernel 1a: e1/e2 row dots --------------------------------
__global__ void k_evec(const float* __restrict__ x,
                       const float* __restrict__ fw1, const float* __restrict__ fw2,
                       const float* __restrict__ gw1, const float* __restrict__ gw2) {
    int gwarp = (blockIdx.x * blockDim.x + threadIdx.x) >> 5;
    int lane  = threadIdx.x & 31;
    const float* xp = x + (size_t)gwarp * DD;
    float v0 = xp[lane], v1 = xp[lane + 32];
    float s0 = v0 * fw1[lane] + v1 * fw1[lane + 32];
    float s1 = v0 * fw2[lane] + v1 * fw2[lane + 32];
    float s2 = v0 * gw1[lane] + v1 * gw1[lane + 32];
    float s3 = v0 * gw2[lane] + v1 * gw2[lane + 32];
    #pragma unroll
    for (int o = 16; o > 0; o >>= 1) {
        s0 += __shfl_xor_sync(0xffffffffu, s0, o);
        s1 += __shfl_xor_sync(0xffffffffu, s1, o);
        s2 += __shfl_xor_sync(0xffffffffu, s2, o);
        s3 += __shfl_xor_sync(0xffffffffu, s3, o);
    }
    if (lane == 0) {
        g_e1f[gwarp] = s0; g_e2f[gwarp] = s1;
        g_e1g[gwarp] = s2; g_e2g[gwarp] = s3;
    }
}

// ---------------- kernel 1b: A_mix -----------------------------------------
__global__ void k_amix(const float* __restrict__ adj, const float* __restrict__ convw) {
    int t = blockIdx.x * blockDim.x + threadIdx.x;
    int base = t * 4;
    int i = base >> 10;
    int j = base & (NN - 1);
    float c0 = convw[0], c1 = convw[1];
    float dsub = c0 + c1;
    float4 a0 = *(const float4*)(adj + base);
    float4 a1 = *(const float4*)(adj + (size_t)NN * NN + base);
    float4 r;
    r.x = c0 * a0.x + c1 * a1.x - ((i == j + 0) ? dsub : 0.0f);
    r.y = c0 * a0.y + c1 * a1.y - ((i == j + 1) ? dsub : 0.0f);
    r.z = c0 * a0.z + c1 * a1.z - ((i == j + 2) ? dsub : 0.0f);
    r.w = c0 * a0.w + c1 * a1.w - ((i == j + 3) ? dsub : 0.0f);
    *(float4*)(g_Amix + base) = r;
}

// ---------------- kernel 1c: W_hat -----------------------------------------
__global__ void k_what(const float* __restrict__ w, const float* __restrict__ d) {
    int t = blockIdx.x * blockDim.x + threadIdx.x;
    int i = t >> 6, j = t & 63;
    float s = 0.0f;
    #pragma unroll 8
    for (int k = 0; k < DD; k++) {
        float dc = fminf(fmaxf(d[k], 0.0f), 1.0f);
        s += w[i * DD + k] * dc * w[j * DD + k];
    }
    g_What[t] = s - ((i == j) ? 1.0f : 0.0f);
}

// ---------------- kernel 1d: sigmoid(alpha) --------------------------------
__global__ void k_salpha(const float* __restrict__ alpha) {
    int t = blockIdx.x * blockDim.x + threadIdx.x;
    if (t < NN) g_salpha[t] = sigm(alpha[t]);
}

// ---------------- kernel 1e: transpose fbs/gbs -----------------------------
__global__ void k_transp(const float* __restrict__ fbs, const float* __restrict__ gbs) {
    __shared__ float t[32][33];
    const float* src = blockIdx.z ? gbs : fbs;
    float* dst = blockIdx.z ? g_bsTg : g_bsTf;
    int x0 = blockIdx.x * 32, y0 = blockIdx.y * 32;
    #pragma unroll
    for (int r = threadIdx.y; r < 32; r += 8)
        t[r][threadIdx.x] = src[(size_t)(y0 + r) * NN + x0 + threadIdx.x];
    __syncthreads();
    #pragma unroll
    for (int r = threadIdx.y; r < 32; r += 8)
        dst[(size_t)(x0 + r) * NN + y0 + threadIdx.x] = t[threadIdx.x][r];
}

// ---------------- kernel 1f: bf16-split vs ---------------------------------
__global__ void k_split(const float* __restrict__ fvs, const float* __restrict__ gvs) {
    int t = blockIdx.x * blockDim.x + threadIdx.x;   // over 2*N*N/4
    int which = t >= (NN * NN / 4);
    int e = which ? t - NN * NN / 4 : t;
    const float4* src = (const float4*)(which ? gvs : fvs);
    float4 a = src[e];
    __nv_bfloat16 h0, l0, h1, l1, h2, l2, h3, l3;
    bf16_split(a.x, h0, l0); bf16_split(a.y, h1, l1);
    bf16_split(a.z, h2, l2); bf16_split(a.w, h3, l3);
    size_t off = (size_t)which * NN * NN + (size_t)e * 4;
    __nv_bfloat162* ph = (__nv_bfloat162*)(g_vHi + off);
    __nv_bfloat162* pl = (__nv_bfloat162*)(g_vLo + off);
    ph[0] = __nv_bfloat162{h0, h1}; ph[1] = __nv_bfloat162{h2, h3};
    pl[0] = __nv_bfloat162{l0, l1}; pl[1] = __nv_bfloat162{l2, l3};
}

// -------- kernel 2: S[b,n,j] = sigmoid(e2[b,n]*e1[b,j] + bsT[n,j]), hi/lo --
__global__ void k_sig(void) {
    int n = blockIdx.x, b = blockIdx.y, which = blockIdx.z;
    int j = threadIdx.x * 4;
    const float* e1 = which ? g_e1g : g_e1f;
    const float* e2 = which ? g_e2g : g_e2f;
    const float* bsT = (which ? g_bsTg : g_bsTf) + (size_t)n * NN + j;
    size_t off = (((size_t)which * BB + b) * NN + n) * NN + j;
    float  a   = e2[b * NN + n];
    float4 e1v = *(const float4*)(e1 + b * NN + j);
    float4 bv  = *(const float4*)bsT;
    float sx = sigm(a * e1v.x + bv.x);
    float sy = sigm(a * e1v.y + bv.y);
    float sz = sigm(a * e1v.z + bv.z);
    float sw = sigm(a * e1v.w + bv.w);
    __nv_bfloat16 h0, l0, h1, l1, h2, l2, h3, l3;
    bf16_split(sx, h0, l0); bf16_split(sy, h1, l1);
    bf16_split(sz, h2, l2); bf16_split(sw, h3, l3);
    __nv_bfloat162* ph = (__nv_bfloat162*)(g_sHi + off);
    __nv_bfloat162* pl = (__nv_bfloat162*)(g_sLo + off);
    ph[0] = __nv_bfloat162{h0, h1}; ph[1] = __nv_bfloat162{h2, h3};
    pl[0] = __nv_bfloat162{l0, l1}; pl[1] = __nv_bfloat162{l2, l3};
}

// ---------------- kernel 3: bf16x3 mma.sync batched GEMM -------------------
// C[b][i][n] = sum_j vs[i][j] * S[b][n][j]
// Split: C = Ahi*Bhi + Ahi*Blo + Alo*Bhi  (all bf16, fp32 accum)
// CTA 128x128, 8 warps (2x4), warp tile 64x32, K-tile 32, ldmatrix fragments,
// cp.async double buffer, padded smem rows (80B) -> conflict-free ldmatrix.
#define KT     32
#define STRB   80                        // bytes per smem row (64 data + 16 pad)
#define TILE_BYTES (128*STRB)            // 10240
#define STAGE_BYTES (4*TILE_BYTES)       // 40960
#define GEMM_SMEM  (2*STAGE_BYTES)       // 81920

__global__ void __launch_bounds__(256) k_gemm() {
    extern __shared__ char smg[];
    uint32_t smb = smem_u32(smg);
    int tid = threadIdx.x;
    int z = blockIdx.z;
    int b = z & (BB - 1);
    int which = z >> 5;
    const __nv_bfloat16* __restrict__ Ahi = g_vHi + (size_t)which * NN * NN;
    const __nv_bfloat16* __restrict__ Alo = g_vLo + (size_t)which * NN * NN;
    const __nv_bfloat16* __restrict__ Bhi = g_sHi + ((size_t)which * BB + b) * NN * NN;
    const __nv_bfloat16* __restrict__ Blo = g_sLo + ((size_t)which * BB + b) * NN * NN;
    float* __restrict__ C = (which ? g_NG : g_EF) + (size_t)b * NN * NN;
    int i0 = blockIdx.y * 128, n0 = blockIdx.x * 128;

    int wid = tid >> 5, lane = tid & 31;
    int gid = lane >> 2, tg = lane & 3;
    int wm = (wid & 1) * 64, wn = (wid >> 1) * 32;

    // per-lane ldmatrix offsets (within a tile, before mf/p/khalf adds)
    int lr    = lane & 7;
    int lrow8 = (lane >> 3) & 1;        // +8 rows
    int lk8   = (lane >> 4) & 1;        // +8 cols -> +16 bytes
    uint32_t aoff = (uint32_t)((wm + lrow8 * 8 + lr) * STRB + lk8 * 16);
    uint32_t boff = (uint32_t)((wn + lrow8 * 8 + lr) * STRB + lk8 * 16);

    // cp.async mapping: 8 chunks of 16B per thread per stage
    int slot_tile[8], slot_row[8], slot_ch[8];
    #pragma unroll
    for (int it = 0; it < 8; it++) {
        int slot = tid + it * 256;
        slot_tile[it] = slot >> 9;
        int r2 = slot & 511;
        slot_row[it] = r2 >> 2;
        slot_ch[it]  = r2 & 3;
    }

    float acc[4][4][4];
    #pragma unroll
    for (int mf = 0; mf < 4; mf++)
        #pragma unroll
        for (int nf = 0; nf < 4; nf++)
            #pragma unroll
            for (int q = 0; q < 4; q++) acc[mf][nf][q] = 0.0f;

    #define ISSUE_STAGE(S) do {                                                  \
        uint32_t sb_ = smb + ((S) & 1) * STAGE_BYTES;                            \
        int kc_ = (S) * KT;                                                      \
        _Pragma("unroll")                                                        \
        for (int it = 0; it < 8; it++) {                                         \
            int tile = slot_tile[it], row = slot_row[it], ch = slot_ch[it];      \
            const __nv_bfloat16* src =                                           \
                (tile == 0) ? Ahi + (size_t)(i0 + row) * NN :                    \
                (tile == 1) ? Alo + (size_t)(i0 + row) * NN :                    \
                (tile == 2) ? Bhi + (size_t)(n0 + row) * NN :                    \
                              Blo + (size_t)(n0 + row) * NN;                     \
            const char* gp = (const char*)(src + kc_) + ch * 16;                 \
            uint32_t sp = sb_ + (uint32_t)(tile * TILE_BYTES + row * STRB + ch * 16); \
            asm volatile("cp.async.ca.shared.global [%0], [%1], 16;"             \
                         :: "r"(sp), "l"(gp));                                   \
        }                                                                        \
        asm volatile("cp.async.commit_group;");                                  \
    } while (0)

    ISSUE_STAGE(0);
    for (int s = 0; s < NN / KT; s++) {
        if (s < NN / KT - 1) {
            ISSUE_STAGE(s + 1);
            asm volatile("cp.async.wait_group 1;");
        } else {
            asm volatile("cp.async.wait_group 0;");
        }
        __syncthreads();
        uint32_t base = smb + (s & 1) * STAGE_BYTES;
        uint32_t tAh = base, tAl = base + TILE_BYTES;
        uint32_t tBh = base + 2 * TILE_BYTES, tBl = base + 3 * TILE_BYTES;

        #pragma unroll
        for (int kh = 0; kh < 2; kh++) {
            uint32_t kb = (uint32_t)(kh * 32);   // 16 bf16 = 32 bytes
            uint32_t ah[4][4], al[4][4], bh[4][2], bl[4][2];
            #pragma unroll
            for (int mf = 0; mf < 4; mf++) {
                uint32_t ao = aoff + (uint32_t)(mf * 16 * STRB) + kb;
                ldm_x4(ah[mf], tAh + ao);
                ldm_x4(al[mf], tAl + ao);
            }
            #pragma unroll
            for (int p = 0; p < 2; p++) {
                uint32_t bo = boff + (uint32_t)(p * 16 * STRB) + kb;
                uint32_t th[4], tl[4];
                ldm_x4(th, tBh + bo);
                ldm_x4(tl, tBl + bo);
                bh[2*p][0]   = th[0]; bh[2*p][1]   = th[2];
                bh[2*p+1][0] = th[1]; bh[2*p+1][1] = th[3];
                bl[2*p][0]   = tl[0]; bl[2*p][1]   = tl[2];
                bl[2*p+1][0] = tl[1]; bl[2*p+1][1] = tl[3];
            }
            #pragma unroll
            for (int mf = 0; mf < 4; mf++)
                #pragma unroll
                for (int nf = 0; nf < 4; nf++) {
                    mma16(acc[mf][nf], ah[mf], bh[nf]);
                    mma16(acc[mf][nf], ah[mf], bl[nf]);
                    mma16(acc[mf][nf], al[mf], bh[nf]);
                }
        }
        __syncthreads();
    }

    // epilogue: direct float2 stores
    #pragma unroll
    for (int mf = 0; mf < 4; mf++) {
        #pragma unroll
        for (int nf = 0; nf < 4; nf++) {
            int row = i0 + wm + mf * 16 + gid;
            int col = n0 + wn + nf * 8 + tg * 2;
            float2 v0 = make_float2(acc[mf][nf][0], acc[mf][nf][1]);
            float2 v1 = make_float2(acc[mf][nf][2], acc[mf][nf][3]);
            *(float2*)(C + (size_t)row * NN + col)       = v0;
            *(float2*)(C + (size_t)(row + 8) * NN + col) = v1;
        }
    }
}

// ---------------- kernel 4: row softmax; fuse N_hat + Emod -----------------
__global__ void k_soft() {
    int i = blockIdx.x, b = blockIdx.y;
    size_t ro = ((size_t)b * NN + i) * NN;
    int c = threadIdx.x * 4;
    int wid = threadIdx.x >> 5, lane = threadIdx.x & 31;
    __shared__ float sE[8], sN[8];

    float4 ev = *(float4*)(g_EF + ro + c);
    float4 nv = *(float4*)(g_NG + ro + c);

    float mE = fmaxf(fmaxf(ev.x, ev.y), fmaxf(ev.z, ev.w));
    float mN = fmaxf(fmaxf(nv.x, nv.y), fmaxf(nv.z, nv.w));
    #pragma unroll
    for (int o = 16; o > 0; o >>= 1) {
        mE = fmaxf(mE, __shfl_xor_sync(0xffffffffu, mE, o));
        mN = fmaxf(mN, __shfl_xor_sync(0xffffffffu, mN, o));
    }
    if (lane == 0) { sE[wid] = mE; sN[wid] = mN; }
    __syncthreads();
    mE = sE[0]; mN = sN[0];
    #pragma unroll
    for (int wv = 1; wv < 8; wv++) { mE = fmaxf(mE, sE[wv]); mN = fmaxf(mN, sN[wv]); }
    __syncthreads();

    float4 eE, eN;
    eE.x = __expf(ev.x - mE); eE.y = __expf(ev.y - mE);
    eE.z = __expf(ev.z - mE); eE.w = __expf(ev.w - mE);
    eN.x = __expf(nv.x - mN); eN.y = __expf(nv.y - mN);
    eN.z = __expf(nv.z - mN); eN.w = __expf(nv.w - mN);
    float sumE = eE.x + eE.y + eE.z + eE.w;
    float sumN = eN.x + eN.y + eN.z + eN.w;
    #pragma unroll
    for (int o = 16; o > 0; o >>= 1) {
        sumE += __shfl_xor_sync(0xffffffffu, sumE, o);
        sumN += __shfl_xor_sync(0xffffffffu, sumN, o);
    }
    if (lane == 0) { sE[wid] = sumE; sN[wid] = sumN; }
    __syncthreads();
    sumE = 0.0f; sumN = 0.0f;
    #pragma unroll
    for (int wv = 0; wv < 8; wv++) { sumE += sE[wv]; sumN += sN[wv]; }

    float invE = __fdividef(1.0f, sumE);
    float invN = __fdividef(1.0f, sumN);

    float4 se;
    se.x = eE.x * invE; se.y = eE.y * invE; se.z = eE.z * invE; se.w = eE.w * invE;
    float4 nh;
    nh.x = __fdividef(eN.x * invN, se.x + 1e-5f);
    nh.y = __fdividef(eN.y * invN, se.y + 1e-5f);
    nh.z = __fdividef(eN.z * invN, se.z + 1e-5f);
    nh.w = __fdividef(eN.w * invN, se.w + 1e-5f);

    float4 am = *(float4*)(g_Amix + (size_t)i * NN + c);
    float4 em;
    em.x = se.x + am.x - ((c + 0 == i) ? 1.0f : 0.0f);
    em.y = se.y + am.y - ((c + 1 == i) ? 1.0f : 0.0f);
    em.z = se.z + am.z - ((c + 2 == i) ? 1.0f : 0.0f);
    em.w = se.w + am.w - ((c + 3 == i) ? 1.0f : 0.0f);

    *(float4*)(g_EF + ro + c) = em;
    *(float4*)(g_NG + ro + c) = nh;
}

// ---------------- kernel 5: fused finals -----------------------------------
#define K5_SMEM_FLOATS (64*65 + 64*65 + 64*64)
__global__ void __launch_bounds__(256) k_final(const float* __restrict__ x,
                                               const float* __restrict__ x0,
                                               const float* __restrict__ convb,
                                               float* __restrict__ out) {
    extern __shared__ float smf[];
    float* Es = smf;
    float* Ns = smf + 64 * 65;
    float* xs = smf + 2 * 64 * 65;

    int b = blockIdx.y, i0 = blockIdx.x * 64;
    int tid = threadIdx.x;
    int il = tid >> 2, cg = tid & 3, c0 = cg * 16;
    const float* xr = x    + (size_t)b * NN * DD;
    const float* Em = g_EF + (size_t)b * NN * NN;
    const float* Nh = g_NG + (size_t)b * NN * NN;

    float af[16], ag[16];
    #pragma unroll
    for (int q = 0; q < 16; q++) { af[q] = 0.0f; ag[q] = 0.0f; }

    for (int jc = 0; jc < 16; jc++) {
        #pragma unroll
        for (int q = 0; q < 4; q++) {
            int lin = tid + q * 256;
            int row = lin >> 4, cc = (lin & 15) * 4;
            float4 ev = *(const float4*)(Em + (size_t)(i0 + row) * NN + jc * 64 + cc);
            Es[row * 65 + cc + 0] = ev.x; Es[row * 65 + cc + 1] = ev.y;
            Es[row * 65 + cc + 2] = ev.z; Es[row * 65 + cc + 3] = ev.w;
            float4 nv = *(const float4*)(Nh + (size_t)(i0 + row) * NN + jc * 64 + cc);
            Ns[row * 65 + cc + 0] = nv.x; Ns[row * 65 + cc + 1] = nv.y;
            Ns[row * 65 + cc + 2] = nv.z; Ns[row * 65 + cc + 3] = nv.w;
            *(float4*)&xs[row * 64 + cc] =
                *(const float4*)(xr + (size_t)(jc * 64 + row) * DD + cc);
        }
        __syncthreads();
        #pragma unroll 8
        for (int j = 0; j < 64; j++) {
            float cf  = Es[il * 65 + j];
            float cgv = Ns[il * 65 + j];
            #pragma unroll
            for (int q = 0; q < 4; q++) {
                float4 xv = *(float4*)&xs[j * 64 + c0 + q * 4];
                af[q * 4 + 0] += cf * xv.x;  af[q * 4 + 1] += cf * xv.y;
                af[q * 4 + 2] += cf * xv.z;  af[q * 4 + 3] += cf * xv.w;
                ag[q * 4 + 0] += cgv * xv.x; ag[q * 4 + 1] += cgv * xv.y;
                ag[q * 4 + 2] += cgv * xv.z; ag[q * 4 + 3] += cgv * xv.w;
            }
        }
        __syncthreads();
    }

    #pragma unroll
    for (int q = 0; q < 4; q++) {
        int lin = tid + q * 256;
        int row = lin >> 4, cc = (lin & 15) * 4;
        *(float4*)&xs[row * 64 + cc] = *(const float4*)(g_What + row * DD + cc);
        float4 xiv = *(const float4*)(xr + (size_t)(i0 + row) * DD + cc);
        Es[row * 65 + cc + 0] = xiv.x; Es[row * 65 + cc + 1] = xiv.y;
        Es[row * 65 + cc + 2] = xiv.z; Es[row * 65 + cc + 3] = xiv.w;
    }
    __syncthreads();
    #pragma unroll 8
    for (int k = 0; k < DD; k++) {
        float xik = Es[il * 65 + k];
        #pragma unroll
        for (int q = 0; q < 4; q++) {
            float4 wv = *(float4*)&xs[k * 64 + c0 + q * 4];
            af[q * 4 + 0] += xik * wv.x; af[q * 4 + 1] += xik * wv.y;
            af[q * 4 + 2] += xik * wv.z; af[q * 4 + 3] += xik * wv.w;
        }
    }

    float cb = convb[0];
    float sa = g_salpha[i0 + il];
    size_t obase = ((size_t)b * NN + i0 + il) * DD + c0;
    #pragma unroll
    for (int q = 0; q < 4; q++) {
        float4 x0v = *(const float4*)(x0 + obase + q * 4);
        float4 fo, go;
        fo.x = tanhf(af[q * 4 + 0] + cb + x0v.x * sa);
        fo.y = tanhf(af[q * 4 + 1] + cb + x0v.y * sa);
        fo.z = tanhf(af[q * 4 + 2] + cb + x0v.z * sa);
        fo.w = tanhf(af[q * 4 + 3] + cb + x0v.w * sa);
        go.x = tanhf(ag[q * 4 + 0]);
        go.y = tanhf(ag[q * 4 + 1]);
        go.z = tanhf(ag[q * 4 + 2]);
        go.w = tanhf(ag[q * 4 + 3]);
        *(float4*)(out + obase + q * 4)        = fo;
        *(float4*)(out + HALF + obase + q * 4) = go;
    }
}

// ---------------- launch ----------------------------------------------------
extern "C" void kernel_launch(void* const* d_in, const int* in_sizes, int n_in,
                              void* d_out, int out_size) {
    const float* x     = (const float*)d_in[0];
    const float* x0    = (const float*)d_in[1];
    const float* w     = (const float*)d_in[2];
    const float* d     = (const float*)d_in[3];
    const float* alpha = (const float*)d_in[4];
    const float* fw1   = (const float*)d_in[5];
    const float* fw2   = (const float*)d_in[6];
    const float* fvs   = (const float*)d_in[7];
    const float* fbs   = (const float*)d_in[8];
    const float* gw1   = (const float*)d_in[9];
    const float* gw2   = (const float*)d_in[10];
    const float* gvs   = (const float*)d_in[11];
    const float* gbs   = (const float*)d_in[12];
    const float* convw = (const float*)d_in[13];
    const float* convb = (const float*)d_in[14];
    const float* adj   = (const float*)d_in[15];
    float* out = (float*)d_out;

    cudaFuncSetAttribute(k_final, cudaFuncAttributeMaxDynamicSharedMemorySize,
                         K5_SMEM_FLOATS * (int)sizeof(float));
    cudaFuncSetAttribute(k_gemm, cudaFuncAttributeMaxDynamicSharedMemorySize, GEMM_SMEM);

    k_evec  <<<(BB * NN) / 8, 256>>>(x, fw1, fw2, gw1, gw2);
    k_amix  <<<(NN * NN / 4) / 256, 256>>>(adj, convw);
    k_what  <<<(DD * DD) / 256, 256>>>(w, d);
    k_salpha<<<NN / 256, 256>>>(alpha);
    k_transp<<<dim3(32, 32, 2), dim3(32, 8)>>>(fbs, gbs);
    k_split <<<(2 * NN * NN / 4) / 256, 256>>>(fvs, gvs);
    k_sig   <<<dim3(NN, BB, 2), 256>>>();
    k_gemm  <<<dim3(NN / 128, NN / 128, 2 * BB), 256, GEMM_SMEM>>>();
    k_soft  <<<dim3(NN, BB), 256>>>();
    k_final <<<dim3(NN / 64, BB), 256, K5_SMEM_FLOATS * (int)sizeof(float)>>>(x, x0, convb, out);
}